// round 7
// baseline (speedup 1.0000x reference)
#include <cuda_runtime.h>
#include <stdint.h>

#define NN 50000
#define NE 600000
#define NP 3
#define DIM 128

// ---------------- scratch (static device globals; no runtime allocation) ----------------
__device__ float g_x[(size_t)NP * NN * DIM];   // per-path projected features
__device__ float g_z[(size_t)NP * NN * DIM];   // aggregation buffer, then finalized z
__device__ int   g_deg_out[NP * NN];
__device__ int   g_deg_in[NP * NN];
__device__ float g_scores[NP];
__device__ float g_beta[NP];

// ---------------- packed fp32x2 helpers (Blackwell FFMA2 path) ----------------
__device__ __forceinline__ unsigned long long ffma2(unsigned long long a,
                                                    unsigned long long b,
                                                    unsigned long long c) {
    unsigned long long d;
    asm("fma.rn.f32x2 %0, %1, %2, %3;" : "=l"(d) : "l"(a), "l"(b), "l"(c));
    return d;
}
__device__ __forceinline__ unsigned long long pack2(float lo, float hi) {
    unsigned long long r;
    asm("mov.b64 %0, {%1, %2};" : "=l"(r) : "f"(lo), "f"(hi));
    return r;
}
__device__ __forceinline__ float2 unpack2(unsigned long long v) {
    float2 r;
    asm("mov.b64 {%0, %1}, %2;" : "=f"(r.x), "=f"(r.y) : "l"(v));
    return r;
}
__device__ __forceinline__ float tanh_approx(float x) {
    float r;
    asm("tanh.approx.f32 %0, %1;" : "=f"(r) : "f"(x));
    return r;
}

// ---------------- zeroing ----------------
__global__ void zero_z_kernel() {
    size_t i = (size_t)blockIdx.x * blockDim.x + threadIdx.x;
    if (i < (size_t)NP * NN * DIM / 4)
        ((float4*)g_z)[i] = make_float4(0.f, 0.f, 0.f, 0.f);
}
__global__ void zero_misc_kernel() {
    int i = blockIdx.x * blockDim.x + threadIdx.x;
    if (i < NP * NN) { g_deg_out[i] = 0; g_deg_in[i] = 0; }
    if (i < NP) g_scores[i] = 0.f;
}

// ---------------- degree counts ----------------
__global__ void degree_kernel(const int* __restrict__ src, const int* __restrict__ dst) {
    int i = blockIdx.x * blockDim.x + threadIdx.x;
    if (i >= NP * NE) return;
    int p = i / NE;
    atomicAdd(&g_deg_out[p * NN + src[i]], 1);
    atomicAdd(&g_deg_in[p * NN + dst[i]], 1);
}

// ---------------- x = (h * rsqrt(max(deg_out,1))) @ W_p ----------------
// Block = 128 threads, tile = 32 rows x 128 cols, K split in two 64-wide phases.
// Thread (warp w, lane l): rows [8w, 8w+8), cols [4l, 4l+4). f32x2 packed FMA.
__global__ void __launch_bounds__(128) gemm_x_kernel(const float* __restrict__ h,
                                                     const float* __restrict__ Wg) {
    __shared__ float hs[32 * 64];
    __shared__ float ws[64 * 128];
    __shared__ float rs[32];
    const int t = threadIdx.x, lane = t & 31, warp = t >> 5;
    const int p = blockIdx.y;
    const int row0 = blockIdx.x * 32;
    const int c0 = lane * 4;
    const int rbase = warp * 8;

    if (t < 32) {
        int grow = row0 + t;
        int d = (grow < NN) ? g_deg_out[p * NN + grow] : 1;
        rs[t] = rsqrtf((float)(d > 1 ? d : 1));
    }

    unsigned long long acc[8][2];
#pragma unroll
    for (int i = 0; i < 8; i++) { acc[i][0] = 0ull; acc[i][1] = 0ull; }

    for (int ph = 0; ph < 2; ph++) {
        int kb = ph * 64;
        __syncthreads();
#pragma unroll
        for (int i = 0; i < 16; i++) {
            int idx = t + i * 128;
            int kk = idx & 63, rr = idx >> 6;
            int grow = row0 + rr;
            float v = 0.f;
            if (grow < NN) v = h[(size_t)grow * DIM + kb + kk] * rs[rr];
            hs[rr * 64 + kk] = v;
        }
        const float4* wsrc = (const float4*)(Wg + ((size_t)p * DIM + kb) * DIM);
        float4* wdst = (float4*)ws;
#pragma unroll
        for (int i = 0; i < 16; i++) wdst[t + i * 128] = wsrc[t + i * 128];
        __syncthreads();
#pragma unroll 4
        for (int k = 0; k < 64; k++) {
            ulonglong2 wv = *(const ulonglong2*)(ws + k * DIM + c0);
#pragma unroll
            for (int i = 0; i < 8; i++) {
                float hv = hs[(rbase + i) * 64 + k];
                unsigned long long hd = pack2(hv, hv);
                acc[i][0] = ffma2(hd, wv.x, acc[i][0]);
                acc[i][1] = ffma2(hd, wv.y, acc[i][1]);
            }
        }
    }
#pragma unroll
    for (int i = 0; i < 8; i++) {
        int grow = row0 + rbase + i;
        if (grow < NN) {
            float2 a = unpack2(acc[i][0]);
            float2 b = unpack2(acc[i][1]);
            *(float4*)(g_x + ((size_t)p * NN + grow) * DIM + c0) =
                make_float4(a.x, a.y, b.x, b.y);
        }
    }
}

// ---------------- agg[dst] += x[src] via vector reductions ----------------
// One warp per edge; each lane covers 4 of the 128 dims with a single red.v4.
__global__ void scatter_kernel(const int* __restrict__ src, const int* __restrict__ dst) {
    int w = (blockIdx.x * blockDim.x + threadIdx.x) >> 5;
    int lane = threadIdx.x & 31;
    if (w >= NP * NE) return;
    int p = w / NE;
    int s = src[w], d = dst[w];
    const float4 v = *(const float4*)(g_x + ((size_t)p * NN + s) * DIM + lane * 4);
    float* a = g_z + ((size_t)p * NN + d) * DIM + lane * 4;
    asm volatile("red.global.add.v4.f32 [%0], {%1, %2, %3, %4};"
                 :: "l"(a), "f"(v.x), "f"(v.y), "f"(v.z), "f"(v.w) : "memory");
}

// ---------------- finalize z + semantic attention scores ----------------
// Fuses: z = agg*rsqrt(max(deg_in,1)) + b_gc  (stored back to g_z)
//        s[p] += sum_rows tanh(z@w1 + b1)@w2
__global__ void __launch_bounds__(128) score_kernel(const float* __restrict__ bgc,
                                                    const float* __restrict__ w1,
                                                    const float* __restrict__ b1,
                                                    const float* __restrict__ w2) {
    __shared__ float hs[32 * 64];
    __shared__ float ws[64 * 128];
    __shared__ float rs[32];
    __shared__ float wred[4];
    const int t = threadIdx.x, lane = t & 31, warp = t >> 5;
    const int p = blockIdx.y;
    const int row0 = blockIdx.x * 32;
    const int c0 = lane * 4;
    const int rbase = warp * 8;

    if (t < 32) {
        int grow = row0 + t;
        int d = (grow < NN) ? g_deg_in[p * NN + grow] : 1;
        rs[t] = rsqrtf((float)(d > 1 ? d : 1));
    }

    unsigned long long acc[8][2];
#pragma unroll
    for (int i = 0; i < 8; i++) { acc[i][0] = 0ull; acc[i][1] = 0ull; }

    for (int ph = 0; ph < 2; ph++) {
        int kb = ph * 64;
        __syncthreads();
#pragma unroll
        for (int i = 0; i < 16; i++) {
            int idx = t + i * 128;
            int kk = idx & 63, rr = idx >> 6;
            int grow = row0 + rr;
            float v = 0.f;
            if (grow < NN) {
                size_t off = ((size_t)p * NN + grow) * DIM + kb + kk;
                v = g_z[off] * rs[rr] + bgc[p * DIM + kb + kk];
                g_z[off] = v;  // finalized z for the output pass
            }
            hs[rr * 64 + kk] = v;
        }
        const float4* wsrc = (const float4*)(w1 + (size_t)kb * DIM);
        float4* wdst = (float4*)ws;
#pragma unroll
        for (int i = 0; i < 16; i++) wdst[t + i * 128] = wsrc[t + i * 128];
        __syncthreads();
#pragma unroll 4
        for (int k = 0; k < 64; k++) {
            ulonglong2 wv = *(const ulonglong2*)(ws + k * DIM + c0);
#pragma unroll
            for (int i = 0; i < 8; i++) {
                float hv = hs[(rbase + i) * 64 + k];
                unsigned long long hd = pack2(hv, hv);
                acc[i][0] = ffma2(hd, wv.x, acc[i][0]);
                acc[i][1] = ffma2(hd, wv.y, acc[i][1]);
            }
        }
    }

    float bb0 = b1[c0], bb1 = b1[c0 + 1], bb2 = b1[c0 + 2], bb3 = b1[c0 + 3];
    float v0 = w2[c0], v1 = w2[c0 + 1], v2 = w2[c0 + 2], v3 = w2[c0 + 3];
    float tsum = 0.f;
#pragma unroll
    for (int i = 0; i < 8; i++) {
        int grow = row0 + rbase + i;
        if (grow < NN) {
            float2 a = unpack2(acc[i][0]);
            float2 b = unpack2(acc[i][1]);
            tsum += tanh_approx(a.x + bb0) * v0 + tanh_approx(a.y + bb1) * v1
                  + tanh_approx(b.x + bb2) * v2 + tanh_approx(b.y + bb3) * v3;
        }
    }
#pragma unroll
    for (int o = 16; o; o >>= 1) tsum += __shfl_xor_sync(0xffffffffu, tsum, o);
    if (lane == 0) wred[warp] = tsum;
    __syncthreads();
    if (t == 0) atomicAdd(&g_scores[p], wred[0] + wred[1] + wred[2] + wred[3]);
}

// ---------------- softmax over the 3 path scores ----------------
__global__ void beta_kernel() {
    if (threadIdx.x == 0 && blockIdx.x == 0) {
        float s0 = g_scores[0] / (float)NN;
        float s1 = g_scores[1] / (float)NN;
        float s2 = g_scores[2] / (float)NN;
        float m = fmaxf(s0, fmaxf(s1, s2));
        float e0 = expf(s0 - m), e1 = expf(s1 - m), e2 = expf(s2 - m);
        float inv = 1.f / (e0 + e1 + e2);
        g_beta[0] = e0 * inv; g_beta[1] = e1 * inv; g_beta[2] = e2 * inv;
    }
}

// ---------------- out = sum_p beta_p * z_p ----------------
__global__ void out_kernel(float* __restrict__ out) {
    int i = blockIdx.x * blockDim.x + threadIdx.x;
    const int n4 = NN * DIM / 4;
    if (i >= n4) return;
    float b0 = g_beta[0], b1v = g_beta[1], b2 = g_beta[2];
    const float4* z = (const float4*)g_z;
    float4 z0 = z[i], z1 = z[(size_t)n4 + i], z2 = z[(size_t)2 * n4 + i];
    float4 r;
    r.x = b0 * z0.x + b1v * z1.x + b2 * z2.x;
    r.y = b0 * z0.y + b1v * z1.y + b2 * z2.y;
    r.z = b0 * z0.z + b1v * z1.z + b2 * z2.z;
    r.w = b0 * z0.w + b1v * z1.w + b2 * z2.w;
    ((float4*)out)[i] = r;
}

// ---------------- launcher (default stream, graph-capturable) ----------------
extern "C" void kernel_launch(void* const* d_in, const int* in_sizes, int n_in,
                              void* d_out, int out_size) {
    (void)in_sizes; (void)n_in; (void)out_size;
    const float* h   = (const float*)d_in[0];
    const float* Wg  = (const float*)d_in[1];
    const float* bgc = (const float*)d_in[2];
    const float* w1  = (const float*)d_in[3];
    const float* b1  = (const float*)d_in[4];
    const float* w2  = (const float*)d_in[5];
    const int* esrc  = (const int*)d_in[6];
    const int* edst  = (const int*)d_in[7];

    int zb = (NP * NN * DIM / 4 + 255) / 256;
    zero_z_kernel<<<zb, 256>>>();
    zero_misc_kernel<<<(NP * NN + 255) / 256, 256>>>();
    degree_kernel<<<(NP * NE + 255) / 256, 256>>>(esrc, edst);

    dim3 gg((NN + 31) / 32, NP);
    gemm_x_kernel<<<gg, 128>>>(h, Wg);

    long long tthreads = (long long)NP * NE * 32;  // one warp per edge
    scatter_kernel<<<(unsigned)((tthreads + 255) / 256), 256>>>(esrc, edst);

    score_kernel<<<gg, 128>>>(bgc, w1, b1, w2);
    beta_kernel<<<1, 32>>>();
    out_kernel<<<(NN * DIM / 4 + 255) / 256, 256>>>((float*)d_out);
}

// round 8
// speedup vs baseline: 1.4177x; 1.4177x over previous
#include <cuda_runtime.h>
#include <stdint.h>

#define NN 50000
#define NE 600000
#define NP 3
#define DIM 128
#define NPN (NP * NN)          // 150000
#define NTE (NP * NE)          // 1800000
#define SCAN_BLKS ((NPN + 1023) / 1024)   // 147

// ---------------- scratch (static device globals; no runtime allocation) ----------------
__device__ float g_x[(size_t)NP * NN * DIM];   // per-path projected features
__device__ float g_z[(size_t)NP * NN * DIM];   // finalized z (written once by gather)
__device__ int   g_deg_out[NPN];
__device__ int   g_cnt[NPN];                   // in-degree histogram
__device__ int   g_off[NPN];                   // CSR row offsets (exclusive scan of g_cnt)
__device__ int   g_cursor[NPN];                // placement cursors
__device__ int   g_csr_src[NTE];               // src ids grouped by dst
__device__ int   g_bsum[SCAN_BLKS];
__device__ int   g_boff[SCAN_BLKS];
__device__ float g_scores[NP];
__device__ float g_beta[NP];

// ---------------- packed fp32x2 helpers (Blackwell FFMA2 path) ----------------
__device__ __forceinline__ unsigned long long ffma2(unsigned long long a,
                                                    unsigned long long b,
                                                    unsigned long long c) {
    unsigned long long d;
    asm("fma.rn.f32x2 %0, %1, %2, %3;" : "=l"(d) : "l"(a), "l"(b), "l"(c));
    return d;
}
__device__ __forceinline__ unsigned long long pack2(float lo, float hi) {
    unsigned long long r;
    asm("mov.b64 %0, {%1, %2};" : "=l"(r) : "f"(lo), "f"(hi));
    return r;
}
__device__ __forceinline__ float2 unpack2(unsigned long long v) {
    float2 r;
    asm("mov.b64 {%0, %1}, %2;" : "=f"(r.x), "=f"(r.y) : "l"(v));
    return r;
}
__device__ __forceinline__ float tanh_approx(float x) {
    float r;
    asm("tanh.approx.f32 %0, %1;" : "=f"(r) : "f"(x));
    return r;
}

// ---------------- init ----------------
__global__ void zero_misc_kernel() {
    int i = blockIdx.x * blockDim.x + threadIdx.x;
    if (i < NPN) { g_deg_out[i] = 0; g_cnt[i] = 0; }
    if (i < NP) g_scores[i] = 0.f;
}

// ---------------- degree histograms ----------------
__global__ void degree_kernel(const int* __restrict__ src, const int* __restrict__ dst) {
    int i = blockIdx.x * blockDim.x + threadIdx.x;
    if (i >= NTE) return;
    int p = i / NE;
    atomicAdd(&g_deg_out[p * NN + src[i]], 1);
    atomicAdd(&g_cnt[p * NN + dst[i]], 1);
}

// ---------------- two-level exclusive scan of g_cnt -> g_off ----------------
__global__ void scan_block_kernel() {           // grid=SCAN_BLKS, block=1024
    __shared__ int wsum[32];
    int b = blockIdx.x, t = threadIdx.x;
    int i = b * 1024 + t;
    int v = (i < NPN) ? g_cnt[i] : 0;
    int lane = t & 31, w = t >> 5;
    int x = v;
#pragma unroll
    for (int o = 1; o < 32; o <<= 1) {
        int y = __shfl_up_sync(0xffffffffu, x, o);
        if (lane >= o) x += y;
    }
    if (lane == 31) wsum[w] = x;
    __syncthreads();
    if (w == 0) {
        int s = wsum[lane];
#pragma unroll
        for (int o = 1; o < 32; o <<= 1) {
            int y = __shfl_up_sync(0xffffffffu, s, o);
            if (lane >= o) s += y;
        }
        wsum[lane] = s;
    }
    __syncthreads();
    int excl = x - v + (w > 0 ? wsum[w - 1] : 0);
    if (i < NPN) g_off[i] = excl;
    if (t == 1023) g_bsum[b] = excl + v;
}
__global__ void scan_top_kernel() {             // 1 block, 256 threads
    __shared__ int wsum[32];
    int t = threadIdx.x;
    int v = (t < SCAN_BLKS) ? g_bsum[t] : 0;
    int lane = t & 31, w = t >> 5;
    int x = v;
#pragma unroll
    for (int o = 1; o < 32; o <<= 1) {
        int y = __shfl_up_sync(0xffffffffu, x, o);
        if (lane >= o) x += y;
    }
    if (lane == 31) wsum[w] = x;
    __syncthreads();
    if (w == 0) {
        int s = wsum[lane];
#pragma unroll
        for (int o = 1; o < 32; o <<= 1) {
            int y = __shfl_up_sync(0xffffffffu, s, o);
            if (lane >= o) s += y;
        }
        wsum[lane] = s;
    }
    __syncthreads();
    if (t < SCAN_BLKS) g_boff[t] = x - v + (w > 0 ? wsum[w - 1] : 0);
}
__global__ void scan_add_kernel() {
    int i = blockIdx.x * blockDim.x + threadIdx.x;
    if (i >= NPN) return;
    int off = g_off[i] + g_boff[i >> 10];
    g_off[i] = off;
    g_cursor[i] = off;
}

// ---------------- CSR placement: group src ids by dst ----------------
__global__ void place_kernel(const int* __restrict__ src, const int* __restrict__ dst) {
    int i = blockIdx.x * blockDim.x + threadIdx.x;
    if (i >= NTE) return;
    int p = i / NE;
    int pos = atomicAdd(&g_cursor[p * NN + dst[i]], 1);
    g_csr_src[pos] = src[i];
}

// ---------------- x = (h * rsqrt(max(deg_out,1))) @ W_p ----------------
// Block = 128 threads, tile = 32 rows x 128 cols, K in two 64-wide phases.
// h tile stored PRE-PACKED as f32x2 {v,v} -> inner loop has no dup MOVs.
__global__ void __launch_bounds__(128) gemm_x_kernel(const float* __restrict__ h,
                                                     const float* __restrict__ Wg) {
    __shared__ unsigned long long hs[32 * 64];   // 16 KB, packed {v,v}
    __shared__ float ws[64 * 128];               // 32 KB
    __shared__ float rs[32];
    const int t = threadIdx.x, lane = t & 31, warp = t >> 5;
    const int p = blockIdx.y;
    const int row0 = blockIdx.x * 32;
    const int c0 = lane * 4;
    const int rbase = warp * 8;

    if (t < 32) {
        int grow = row0 + t;
        int d = (grow < NN) ? g_deg_out[p * NN + grow] : 1;
        rs[t] = rsqrtf((float)(d > 1 ? d : 1));
    }

    unsigned long long acc[8][2];
#pragma unroll
    for (int i = 0; i < 8; i++) { acc[i][0] = 0ull; acc[i][1] = 0ull; }

    for (int ph = 0; ph < 2; ph++) {
        int kb = ph * 64;
        __syncthreads();
#pragma unroll
        for (int i = 0; i < 16; i++) {
            int idx = t + i * 128;
            int kk = idx & 63, rr = idx >> 6;
            int grow = row0 + rr;
            float v = 0.f;
            if (grow < NN) v = h[(size_t)grow * DIM + kb + kk] * rs[rr];
            hs[rr * 64 + kk] = pack2(v, v);
        }
        const float4* wsrc = (const float4*)(Wg + ((size_t)p * DIM + kb) * DIM);
        float4* wdst = (float4*)ws;
#pragma unroll
        for (int i = 0; i < 16; i++) wdst[t + i * 128] = wsrc[t + i * 128];
        __syncthreads();
#pragma unroll 4
        for (int k = 0; k < 64; k++) {
            ulonglong2 wv = *(const ulonglong2*)(ws + k * DIM + c0);
#pragma unroll
            for (int i = 0; i < 8; i++) {
                unsigned long long hd = hs[(rbase + i) * 64 + k];
                acc[i][0] = ffma2(hd, wv.x, acc[i][0]);
                acc[i][1] = ffma2(hd, wv.y, acc[i][1]);
            }
        }
    }
#pragma unroll
    for (int i = 0; i < 8; i++) {
        int grow = row0 + rbase + i;
        if (grow < NN) {
            float2 a = unpack2(acc[i][0]);
            float2 b = unpack2(acc[i][1]);
            *(float4*)(g_x + ((size_t)p * NN + grow) * DIM + c0) =
                make_float4(a.x, a.y, b.x, b.y);
        }
    }
}

// ---------------- CSR gather: z = rsqrt(max(deg_in,1)) * sum_{e in-edges} x[src] + b_gc ----
// One warp per (path,node); lane owns 4 of 128 dims. Writes finalized z (no atomics, no zeroing).
__global__ void __launch_bounds__(256) gather_kernel(const float* __restrict__ bgc) {
    int w = (blockIdx.x * blockDim.x + threadIdx.x) >> 5;
    int lane = threadIdx.x & 31;
    if (w >= NPN) return;
    int p = w / NN;
    int start = g_off[w];
    int deg = g_cnt[w];
    int end = start + deg;

    const float4* xb = (const float4*)(g_x + (size_t)p * NN * DIM);
    float4 acc = make_float4(0.f, 0.f, 0.f, 0.f);
    int e = start;
    for (; e + 1 < end; e += 2) {
        int s0 = g_csr_src[e];
        int s1 = g_csr_src[e + 1];
        float4 a = xb[(size_t)s0 * 32 + lane];
        float4 b = xb[(size_t)s1 * 32 + lane];
        acc.x += a.x; acc.y += a.y; acc.z += a.z; acc.w += a.w;
        acc.x += b.x; acc.y += b.y; acc.z += b.z; acc.w += b.w;
    }
    if (e < end) {
        int s0 = g_csr_src[e];
        float4 a = xb[(size_t)s0 * 32 + lane];
        acc.x += a.x; acc.y += a.y; acc.z += a.z; acc.w += a.w;
    }
    float r = rsqrtf((float)(deg > 1 ? deg : 1));
    float4 bb = *(const float4*)(bgc + p * DIM + lane * 4);
    float4 zz;
    zz.x = acc.x * r + bb.x;
    zz.y = acc.y * r + bb.y;
    zz.z = acc.z * r + bb.z;
    zz.w = acc.w * r + bb.w;
    *(float4*)(g_z + (size_t)w * DIM + lane * 4) = zz;
}

// ---------------- semantic attention scores: s[p] += sum_rows tanh(z@w1+b1)@w2 ----------------
__global__ void __launch_bounds__(128) score_kernel(const float* __restrict__ w1,
                                                    const float* __restrict__ b1,
                                                    const float* __restrict__ w2) {
    __shared__ unsigned long long hs[32 * 64];
    __shared__ float ws[64 * 128];
    __shared__ float wred[4];
    const int t = threadIdx.x, lane = t & 31, warp = t >> 5;
    const int p = blockIdx.y;
    const int row0 = blockIdx.x * 32;
    const int c0 = lane * 4;
    const int rbase = warp * 8;

    unsigned long long acc[8][2];
#pragma unroll
    for (int i = 0; i < 8; i++) { acc[i][0] = 0ull; acc[i][1] = 0ull; }

    for (int ph = 0; ph < 2; ph++) {
        int kb = ph * 64;
        __syncthreads();
#pragma unroll
        for (int i = 0; i < 16; i++) {
            int idx = t + i * 128;
            int kk = idx & 63, rr = idx >> 6;
            int grow = row0 + rr;
            float v = 0.f;
            if (grow < NN) v = g_z[((size_t)p * NN + grow) * DIM + kb + kk];
            hs[rr * 64 + kk] = pack2(v, v);
        }
        const float4* wsrc = (const float4*)(w1 + (size_t)kb * DIM);
        float4* wdst = (float4*)ws;
#pragma unroll
        for (int i = 0; i < 16; i++) wdst[t + i * 128] = wsrc[t + i * 128];
        __syncthreads();
#pragma unroll 4
        for (int k = 0; k < 64; k++) {
            ulonglong2 wv = *(const ulonglong2*)(ws + k * DIM + c0);
#pragma unroll
            for (int i = 0; i < 8; i++) {
                unsigned long long hd = hs[(rbase + i) * 64 + k];
                acc[i][0] = ffma2(hd, wv.x, acc[i][0]);
                acc[i][1] = ffma2(hd, wv.y, acc[i][1]);
            }
        }
    }

    float bb0 = b1[c0], bb1 = b1[c0 + 1], bb2 = b1[c0 + 2], bb3 = b1[c0 + 3];
    float v0 = w2[c0], v1 = w2[c0 + 1], v2 = w2[c0 + 2], v3 = w2[c0 + 3];
    float tsum = 0.f;
#pragma unroll
    for (int i = 0; i < 8; i++) {
        int grow = row0 + rbase + i;
        if (grow < NN) {
            float2 a = unpack2(acc[i][0]);
            float2 b = unpack2(acc[i][1]);
            tsum += tanh_approx(a.x + bb0) * v0 + tanh_approx(a.y + bb1) * v1
                  + tanh_approx(b.x + bb2) * v2 + tanh_approx(b.y + bb3) * v3;
        }
    }
#pragma unroll
    for (int o = 16; o; o >>= 1) tsum += __shfl_xor_sync(0xffffffffu, tsum, o);
    if (lane == 0) wred[warp] = tsum;
    __syncthreads();
    if (t == 0) atomicAdd(&g_scores[p], wred[0] + wred[1] + wred[2] + wred[3]);
}

// ---------------- softmax over the 3 path scores ----------------
__global__ void beta_kernel() {
    if (threadIdx.x == 0 && blockIdx.x == 0) {
        float s0 = g_scores[0] / (float)NN;
        float s1 = g_scores[1] / (float)NN;
        float s2 = g_scores[2] / (float)NN;
        float m = fmaxf(s0, fmaxf(s1, s2));
        float e0 = expf(s0 - m), e1 = expf(s1 - m), e2 = expf(s2 - m);
        float inv = 1.f / (e0 + e1 + e2);
        g_beta[0] = e0 * inv; g_beta[1] = e1 * inv; g_beta[2] = e2 * inv;
    }
}

// ---------------- out = sum_p beta_p * z_p ----------------
__global__ void out_kernel(float* __restrict__ out) {
    int i = blockIdx.x * blockDim.x + threadIdx.x;
    const int n4 = NN * DIM / 4;
    if (i >= n4) return;
    float b0 = g_beta[0], b1v = g_beta[1], b2 = g_beta[2];
    const float4* z = (const float4*)g_z;
    float4 z0 = z[i], z1 = z[(size_t)n4 + i], z2 = z[(size_t)2 * n4 + i];
    float4 r;
    r.x = b0 * z0.x + b1v * z1.x + b2 * z2.x;
    r.y = b0 * z0.y + b1v * z1.y + b2 * z2.y;
    r.z = b0 * z0.z + b1v * z1.z + b2 * z2.z;
    r.w = b0 * z0.w + b1v * z1.w + b2 * z2.w;
    ((float4*)out)[i] = r;
}

// ---------------- launcher (default stream, graph-capturable) ----------------
extern "C" void kernel_launch(void* const* d_in, const int* in_sizes, int n_in,
                              void* d_out, int out_size) {
    (void)in_sizes; (void)n_in; (void)out_size;
    const float* h   = (const float*)d_in[0];
    const float* Wg  = (const float*)d_in[1];
    const float* bgc = (const float*)d_in[2];
    const float* w1  = (const float*)d_in[3];
    const float* b1  = (const float*)d_in[4];
    const float* w2  = (const float*)d_in[5];
    const int* esrc  = (const int*)d_in[6];
    const int* edst  = (const int*)d_in[7];

    zero_misc_kernel<<<(NPN + 255) / 256, 256>>>();
    degree_kernel<<<(NTE + 255) / 256, 256>>>(esrc, edst);

    // CSR build
    scan_block_kernel<<<SCAN_BLKS, 1024>>>();
    scan_top_kernel<<<1, 256>>>();
    scan_add_kernel<<<(NPN + 255) / 256, 256>>>();
    place_kernel<<<(NTE + 255) / 256, 256>>>(esrc, edst);

    // per-path projection GEMM
    dim3 gg((NN + 31) / 32, NP);
    gemm_x_kernel<<<gg, 128>>>(h, Wg);

    // CSR gather + finalize z
    gather_kernel<<<(NPN * 32 + 255) / 256, 256>>>(bgc);

    // semantic attention
    score_kernel<<<gg, 128>>>(w1, b1, w2);
    beta_kernel<<<1, 32>>>();
    out_kernel<<<(NN * DIM / 4 + 255) / 256, 256>>>((float*)d_out);
}

// round 9
// speedup vs baseline: 1.4889x; 1.0502x over previous
#include <cuda_runtime.h>
#include <stdint.h>

#define NN 50000
#define NE 600000
#define NP 3
#define DIM 128
#define NPN (NP * NN)          // 150000
#define NTE (NP * NE)          // 1800000
#define SCAN_BLKS ((NPN + 1023) / 1024)   // 147

// ---------------- scratch (static device globals; no runtime allocation) ----------------
__device__ float g_x[(size_t)NP * NN * DIM];   // per-path projected features
__device__ float g_z[(size_t)NP * NN * DIM];   // finalized z (written once by gather)
__device__ int   g_deg_out[NPN];
__device__ int   g_cnt[NPN];                   // in-degree histogram
__device__ int   g_off[NPN];                   // CSR row offsets (exclusive scan of g_cnt)
__device__ int   g_cursor[NPN];                // placement cursors
__device__ int   g_csr_src[NTE];               // src ids grouped by dst
__device__ int   g_bsum[SCAN_BLKS];
__device__ int   g_boff[SCAN_BLKS];
__device__ float g_scores[NP];
__device__ float g_beta[NP];

// ---------------- packed fp32x2 helpers (Blackwell FFMA2 path) ----------------
__device__ __forceinline__ unsigned long long ffma2(unsigned long long a,
                                                    unsigned long long b,
                                                    unsigned long long c) {
    unsigned long long d;
    asm("fma.rn.f32x2 %0, %1, %2, %3;" : "=l"(d) : "l"(a), "l"(b), "l"(c));
    return d;
}
__device__ __forceinline__ unsigned long long pack2(float lo, float hi) {
    unsigned long long r;
    asm("mov.b64 %0, {%1, %2};" : "=l"(r) : "f"(lo), "f"(hi));
    return r;
}
__device__ __forceinline__ float2 unpack2(unsigned long long v) {
    float2 r;
    asm("mov.b64 {%0, %1}, %2;" : "=f"(r.x), "=f"(r.y) : "l"(v));
    return r;
}
__device__ __forceinline__ float tanh_approx(float x) {
    float r;
    asm("tanh.approx.f32 %0, %1;" : "=f"(r) : "f"(x));
    return r;
}

// ---------------- init ----------------
__global__ void zero_misc_kernel() {
    int i = blockIdx.x * blockDim.x + threadIdx.x;
    if (i < NPN) { g_deg_out[i] = 0; g_cnt[i] = 0; }
    if (i < NP) g_scores[i] = 0.f;
}

// ---------------- degree histograms (split so the two chains can fork) ----------------
__global__ void degree_src_kernel(const int* __restrict__ src) {
    int i = blockIdx.x * blockDim.x + threadIdx.x;
    if (i >= NTE) return;
    int p = i / NE;
    atomicAdd(&g_deg_out[p * NN + src[i]], 1);
}
__global__ void degree_dst_kernel(const int* __restrict__ dst) {
    int i = blockIdx.x * blockDim.x + threadIdx.x;
    if (i >= NTE) return;
    int p = i / NE;
    atomicAdd(&g_cnt[p * NN + dst[i]], 1);
}

// ---------------- two-level exclusive scan of g_cnt -> g_off ----------------
__global__ void scan_block_kernel() {           // grid=SCAN_BLKS, block=1024
    __shared__ int wsum[32];
    int b = blockIdx.x, t = threadIdx.x;
    int i = b * 1024 + t;
    int v = (i < NPN) ? g_cnt[i] : 0;
    int lane = t & 31, w = t >> 5;
    int x = v;
#pragma unroll
    for (int o = 1; o < 32; o <<= 1) {
        int y = __shfl_up_sync(0xffffffffu, x, o);
        if (lane >= o) x += y;
    }
    if (lane == 31) wsum[w] = x;
    __syncthreads();
    if (w == 0) {
        int s = wsum[lane];
#pragma unroll
        for (int o = 1; o < 32; o <<= 1) {
            int y = __shfl_up_sync(0xffffffffu, s, o);
            if (lane >= o) s += y;
        }
        wsum[lane] = s;
    }
    __syncthreads();
    int excl = x - v + (w > 0 ? wsum[w - 1] : 0);
    if (i < NPN) g_off[i] = excl;
    if (t == 1023) g_bsum[b] = excl + v;
}
__global__ void scan_top_kernel() {             // 1 block, 256 threads
    __shared__ int wsum[32];
    int t = threadIdx.x;
    int v = (t < SCAN_BLKS) ? g_bsum[t] : 0;
    int lane = t & 31, w = t >> 5;
    int x = v;
#pragma unroll
    for (int o = 1; o < 32; o <<= 1) {
        int y = __shfl_up_sync(0xffffffffu, x, o);
        if (lane >= o) x += y;
    }
    if (lane == 31) wsum[w] = x;
    __syncthreads();
    if (w == 0) {
        int s = wsum[lane];
#pragma unroll
        for (int o = 1; o < 32; o <<= 1) {
            int y = __shfl_up_sync(0xffffffffu, s, o);
            if (lane >= o) s += y;
        }
        wsum[lane] = s;
    }
    __syncthreads();
    if (t < SCAN_BLKS) g_boff[t] = x - v + (w > 0 ? wsum[w - 1] : 0);
}
__global__ void scan_add_kernel() {
    int i = blockIdx.x * blockDim.x + threadIdx.x;
    if (i >= NPN) return;
    int off = g_off[i] + g_boff[i >> 10];
    g_off[i] = off;
    g_cursor[i] = off;
}

// ---------------- CSR placement: group src ids by dst ----------------
__global__ void place_kernel(const int* __restrict__ src, const int* __restrict__ dst) {
    int i = blockIdx.x * blockDim.x + threadIdx.x;
    if (i >= NTE) return;
    int p = i / NE;
    int pos = atomicAdd(&g_cursor[p * NN + dst[i]], 1);
    g_csr_src[pos] = src[i];
}

// ---------------- x = (h * rsqrt(max(deg_out,1))) @ W_p ----------------
// Block = 128 threads, tile = 32 rows x 128 cols, K in two 64-wide phases.
// h tile pre-packed as f32x2 {v,v}; inner loop reads TWO k-steps per LDS.128
// broadcast so the shared crossbar no longer binds before the fma pipe.
__global__ void __launch_bounds__(128) gemm_x_kernel(const float* __restrict__ h,
                                                     const float* __restrict__ Wg) {
    __shared__ unsigned long long hs[32 * 64];   // 16 KB, packed {v,v}
    __shared__ float ws[64 * 128];               // 32 KB
    __shared__ float rs[32];
    const int t = threadIdx.x, lane = t & 31, warp = t >> 5;
    const int p = blockIdx.y;
    const int row0 = blockIdx.x * 32;
    const int c0 = lane * 4;
    const int rbase = warp * 8;

    if (t < 32) {
        int grow = row0 + t;
        int d = (grow < NN) ? g_deg_out[p * NN + grow] : 1;
        rs[t] = rsqrtf((float)(d > 1 ? d : 1));
    }

    unsigned long long acc[8][2];
#pragma unroll
    for (int i = 0; i < 8; i++) { acc[i][0] = 0ull; acc[i][1] = 0ull; }

    for (int ph = 0; ph < 2; ph++) {
        int kb = ph * 64;
        __syncthreads();
#pragma unroll
        for (int i = 0; i < 16; i++) {
            int idx = t + i * 128;
            int kk = idx & 63, rr = idx >> 6;
            int grow = row0 + rr;
            float v = 0.f;
            if (grow < NN) v = h[(size_t)grow * DIM + kb + kk] * rs[rr];
            hs[rr * 64 + kk] = pack2(v, v);
        }
        const float4* wsrc = (const float4*)(Wg + ((size_t)p * DIM + kb) * DIM);
        float4* wdst = (float4*)ws;
#pragma unroll
        for (int i = 0; i < 16; i++) wdst[t + i * 128] = wsrc[t + i * 128];
        __syncthreads();
#pragma unroll 4
        for (int k = 0; k < 64; k += 2) {
            ulonglong2 wv0 = *(const ulonglong2*)(ws + k * DIM + c0);
            ulonglong2 wv1 = *(const ulonglong2*)(ws + (k + 1) * DIM + c0);
#pragma unroll
            for (int i = 0; i < 8; i++) {
                ulonglong2 hd = *(const ulonglong2*)&hs[(rbase + i) * 64 + k];
                acc[i][0] = ffma2(hd.x, wv0.x, acc[i][0]);
                acc[i][1] = ffma2(hd.x, wv0.y, acc[i][1]);
                acc[i][0] = ffma2(hd.y, wv1.x, acc[i][0]);
                acc[i][1] = ffma2(hd.y, wv1.y, acc[i][1]);
            }
        }
    }
#pragma unroll
    for (int i = 0; i < 8; i++) {
        int grow = row0 + rbase + i;
        if (grow < NN) {
            float2 a = unpack2(acc[i][0]);
            float2 b = unpack2(acc[i][1]);
            *(float4*)(g_x + ((size_t)p * NN + grow) * DIM + c0) =
                make_float4(a.x, a.y, b.x, b.y);
        }
    }
}

// ---------------- CSR gather: z = rsqrt(max(deg_in,1)) * sum_{in-edges} x[src] + b_gc ----
// One warp per (path,node); lane owns 4 of 128 dims. No atomics, no zeroing.
__global__ void __launch_bounds__(256) gather_kernel(const float* __restrict__ bgc) {
    int w = (blockIdx.x * blockDim.x + threadIdx.x) >> 5;
    int lane = threadIdx.x & 31;
    if (w >= NPN) return;
    int p = w / NN;
    int start = g_off[w];
    int deg = g_cnt[w];
    int end = start + deg;

    const float4* xb = (const float4*)(g_x + (size_t)p * NN * DIM);
    float4 acc = make_float4(0.f, 0.f, 0.f, 0.f);
    int e = start;
    for (; e + 1 < end; e += 2) {
        int s0 = g_csr_src[e];
        int s1 = g_csr_src[e + 1];
        float4 a = xb[(size_t)s0 * 32 + lane];
        float4 b = xb[(size_t)s1 * 32 + lane];
        acc.x += a.x; acc.y += a.y; acc.z += a.z; acc.w += a.w;
        acc.x += b.x; acc.y += b.y; acc.z += b.z; acc.w += b.w;
    }
    if (e < end) {
        int s0 = g_csr_src[e];
        float4 a = xb[(size_t)s0 * 32 + lane];
        acc.x += a.x; acc.y += a.y; acc.z += a.z; acc.w += a.w;
    }
    float r = rsqrtf((float)(deg > 1 ? deg : 1));
    float4 bb = *(const float4*)(bgc + p * DIM + lane * 4);
    float4 zz;
    zz.x = acc.x * r + bb.x;
    zz.y = acc.y * r + bb.y;
    zz.z = acc.z * r + bb.z;
    zz.w = acc.w * r + bb.w;
    *(float4*)(g_z + (size_t)w * DIM + lane * 4) = zz;
}

// ---------------- semantic attention scores: s[p] += sum_rows tanh(z@w1+b1)@w2 ----------------
__global__ void __launch_bounds__(128) score_kernel(const float* __restrict__ w1,
                                                    const float* __restrict__ b1,
                                                    const float* __restrict__ w2) {
    __shared__ unsigned long long hs[32 * 64];
    __shared__ float ws[64 * 128];
    __shared__ float wred[4];
    const int t = threadIdx.x, lane = t & 31, warp = t >> 5;
    const int p = blockIdx.y;
    const int row0 = blockIdx.x * 32;
    const int c0 = lane * 4;
    const int rbase = warp * 8;

    unsigned long long acc[8][2];
#pragma unroll
    for (int i = 0; i < 8; i++) { acc[i][0] = 0ull; acc[i][1] = 0ull; }

    for (int ph = 0; ph < 2; ph++) {
        int kb = ph * 64;
        __syncthreads();
#pragma unroll
        for (int i = 0; i < 16; i++) {
            int idx = t + i * 128;
            int kk = idx & 63, rr = idx >> 6;
            int grow = row0 + rr;
            float v = 0.f;
            if (grow < NN) v = g_z[((size_t)p * NN + grow) * DIM + kb + kk];
            hs[rr * 64 + kk] = pack2(v, v);
        }
        const float4* wsrc = (const float4*)(w1 + (size_t)kb * DIM);
        float4* wdst = (float4*)ws;
#pragma unroll
        for (int i = 0; i < 16; i++) wdst[t + i * 128] = wsrc[t + i * 128];
        __syncthreads();
#pragma unroll 4
        for (int k = 0; k < 64; k += 2) {
            ulonglong2 wv0 = *(const ulonglong2*)(ws + k * DIM + c0);
            ulonglong2 wv1 = *(const ulonglong2*)(ws + (k + 1) * DIM + c0);
#pragma unroll
            for (int i = 0; i < 8; i++) {
                ulonglong2 hd = *(const ulonglong2*)&hs[(rbase + i) * 64 + k];
                acc[i][0] = ffma2(hd.x, wv0.x, acc[i][0]);
                acc[i][1] = ffma2(hd.x, wv0.y, acc[i][1]);
                acc[i][0] = ffma2(hd.y, wv1.x, acc[i][0]);
                acc[i][1] = ffma2(hd.y, wv1.y, acc[i][1]);
            }
        }
    }

    float bb0 = b1[c0], bb1 = b1[c0 + 1], bb2 = b1[c0 + 2], bb3 = b1[c0 + 3];
    float v0 = w2[c0], v1 = w2[c0 + 1], v2 = w2[c0 + 2], v3 = w2[c0 + 3];
    float tsum = 0.f;
#pragma unroll
    for (int i = 0; i < 8; i++) {
        int grow = row0 + rbase + i;
        if (grow < NN) {
            float2 a = unpack2(acc[i][0]);
            float2 b = unpack2(acc[i][1]);
            tsum += tanh_approx(a.x + bb0) * v0 + tanh_approx(a.y + bb1) * v1
                  + tanh_approx(b.x + bb2) * v2 + tanh_approx(b.y + bb3) * v3;
        }
    }
#pragma unroll
    for (int o = 16; o; o >>= 1) tsum += __shfl_xor_sync(0xffffffffu, tsum, o);
    if (lane == 0) wred[warp] = tsum;
    __syncthreads();
    if (t == 0) atomicAdd(&g_scores[p], wred[0] + wred[1] + wred[2] + wred[3]);
}

// ---------------- softmax over the 3 path scores ----------------
__global__ void beta_kernel() {
    if (threadIdx.x == 0 && blockIdx.x == 0) {
        float s0 = g_scores[0] / (float)NN;
        float s1 = g_scores[1] / (float)NN;
        float s2 = g_scores[2] / (float)NN;
        float m = fmaxf(s0, fmaxf(s1, s2));
        float e0 = expf(s0 - m), e1 = expf(s1 - m), e2 = expf(s2 - m);
        float inv = 1.f / (e0 + e1 + e2);
        g_beta[0] = e0 * inv; g_beta[1] = e1 * inv; g_beta[2] = e2 * inv;
    }
}

// ---------------- out = sum_p beta_p * z_p ----------------
__global__ void out_kernel(float* __restrict__ out) {
    int i = blockIdx.x * blockDim.x + threadIdx.x;
    const int n4 = NN * DIM / 4;
    if (i >= n4) return;
    float b0 = g_beta[0], b1v = g_beta[1], b2 = g_beta[2];
    const float4* z = (const float4*)g_z;
    float4 z0 = z[i], z1 = z[(size_t)n4 + i], z2 = z[(size_t)2 * n4 + i];
    float4 r;
    r.x = b0 * z0.x + b1v * z1.x + b2 * z2.x;
    r.y = b0 * z0.y + b1v * z1.y + b2 * z2.y;
    r.z = b0 * z0.z + b1v * z1.z + b2 * z2.z;
    r.w = b0 * z0.w + b1v * z1.w + b2 * z2.w;
    ((float4*)out)[i] = r;
}

// ---------------- launcher (fork/join streams; graph-capturable) ----------------
extern "C" void kernel_launch(void* const* d_in, const int* in_sizes, int n_in,
                              void* d_out, int out_size) {
    (void)in_sizes; (void)n_in; (void)out_size;
    const float* h   = (const float*)d_in[0];
    const float* Wg  = (const float*)d_in[1];
    const float* bgc = (const float*)d_in[2];
    const float* w1  = (const float*)d_in[3];
    const float* b1  = (const float*)d_in[4];
    const float* w2  = (const float*)d_in[5];
    const int* esrc  = (const int*)d_in[6];
    const int* edst  = (const int*)d_in[7];

    // One-time resource creation (first call is the uncaptured correctness
    // run; the captured call reuses these — identical work every call).
    static cudaStream_t s1 = nullptr;
    static cudaEvent_t evFork = nullptr, evJoin = nullptr;
    if (s1 == nullptr) {
        cudaStreamCreateWithFlags(&s1, cudaStreamNonBlocking);
        cudaEventCreateWithFlags(&evFork, cudaEventDisableTiming);
        cudaEventCreateWithFlags(&evJoin, cudaEventDisableTiming);
    }

    zero_misc_kernel<<<(NPN + 255) / 256, 256>>>();

    // fork: CSR build chain on s1, projection GEMM chain on the main stream
    cudaEventRecord(evFork, 0);
    cudaStreamWaitEvent(s1, evFork, 0);

    degree_dst_kernel<<<(NTE + 255) / 256, 256, 0, s1>>>(edst);
    scan_block_kernel<<<SCAN_BLKS, 1024, 0, s1>>>();
    scan_top_kernel<<<1, 256, 0, s1>>>();
    scan_add_kernel<<<(NPN + 255) / 256, 256, 0, s1>>>();
    place_kernel<<<(NTE + 255) / 256, 256, 0, s1>>>(esrc, edst);

    degree_src_kernel<<<(NTE + 255) / 256, 256>>>(esrc);
    dim3 gg((NN + 31) / 32, NP);
    gemm_x_kernel<<<gg, 128>>>(h, Wg);

    // join
    cudaEventRecord(evJoin, s1);
    cudaStreamWaitEvent(0, evJoin, 0);

    // CSR gather + finalize z
    gather_kernel<<<(NPN * 32 + 255) / 256, 256>>>(bgc);

    // semantic attention
    score_kernel<<<gg, 128>>>(w1, b1, w2);
    beta_kernel<<<1, 32>>>();
    out_kernel<<<(NN * DIM / 4 + 255) / 256, 256>>>((float*)d_out);
}